// round 6
// baseline (speedup 1.0000x reference)
#include <cuda_runtime.h>
#include <math.h>

#define VSZ 50257
#define HD  256
#define ESZ 64
#define TT  2048
#define OUTW 50348   // 2 + 64 + 25 + 50257
#define NB  64

// ---------------- device scratch (no allocs allowed) ----------------
__device__ float g_GX[TT*1024];
__device__ float g_Hmat[TT*HD];
__device__ float g_Ecur[TT*HD];
__device__ float g_Z[TT*HD];
__device__ float g_ents[ESZ*HD];
__device__ float g_A[ESZ*HD];
__device__ float g_dists[ESZ];
__device__ float g_hbuf[2][HD];
__device__ float g_pd[NB];
__device__ float g_eh, g_hh;
__device__ float g_R2[2*HD];
__device__ float g_WentT[HD*HD];
__device__ unsigned g_bar_cnt;
__device__ volatile unsigned g_bar_gen;

__device__ __forceinline__ float sigf(float x){ return 1.0f/(1.0f+expf(-x)); }

// grid barrier (64 co-resident CTAs), monotonic generation
__device__ __forceinline__ void gridbar(unsigned target){
    __syncthreads();
    if (threadIdx.x == 0){
        __threadfence();
        unsigned prev = atomicAdd(&g_bar_cnt, 1u);
        if (prev == NB-1u){ g_bar_cnt = 0u; __threadfence(); g_bar_gen = target; }
        else { while (g_bar_gen < target) {} __threadfence(); }
    }
    __syncthreads();
}

// block-wide reduce over 256 threads; returns sum to all threads
__device__ __forceinline__ float bred(float v, float* sred, int tid){
    #pragma unroll
    for (int o=16;o;o>>=1) v += __shfl_down_sync(0xffffffffu, v, o);
    if ((tid&31)==0) sred[tid>>5]=v;
    __syncthreads();
    if (tid==0){ float s=0.f; for(int i=0;i<8;++i) s+=sred[i]; sred[0]=s; }
    __syncthreads();
    float r = sred[0];
    __syncthreads();
    return r;
}

// ---------------- prep ----------------
__global__ void k_prep(const float* __restrict__ ents0, const float* __restrict__ dist0,
                       const float* __restrict__ Went, const float* __restrict__ r_emb,
                       const float* __restrict__ Wr)
{
    const int b = blockIdx.x, tid = threadIdx.x;
    if (b == ESZ){
        for (int r=0;r<2;++r){
            float s=0.f;
            for (int k=0;k<HD;++k) s += r_emb[r*HD+k]*Wr[k*HD+tid];
            g_R2[r*HD+tid] = s;
        }
        if (tid==0){ g_bar_cnt=0u; g_bar_gen=0u; }
        if (tid<ESZ) g_dists[tid] = dist0[tid];
        g_hbuf[0][tid] = 0.f; g_hbuf[1][tid] = 0.f;
    } else {
        const int e = b;
        g_ents[e*HD+tid] = ents0[e*HD+tid];
        float s=0.f;
        for (int k=0;k<HD;++k) s += ents0[e*HD+k]*Went[k*HD+tid];
        g_A[e*HD+tid] = s;
        #pragma unroll
        for (int r=0;r<4;++r){
            const int j = 4*e + r;
            g_WentT[j*HD+tid] = Went[tid*HD+j];
        }
    }
}

// ---------------- GX[t][row] = W_ih[row]·emb[tok_t] + b_ih + b_hh ----------------
__global__ void __launch_bounds__(256) k_gx(const float* __restrict__ Wih,
                                            const float* __restrict__ emb,
                                            const int*   __restrict__ tokens,
                                            const float* __restrict__ bih,
                                            const float* __restrict__ bhh)
{
    __shared__ float sx[HD];
    const int tid = threadIdx.x, t = blockIdx.x;
    const int w = tid>>5, lane = tid&31;
    const int tok = tokens[t];
    sx[tid] = emb[(size_t)tok*HD + tid];
    __syncthreads();
    for (int r0=0;r0<1024;r0+=64){
        #pragma unroll
        for (int rr=0;rr<8;++rr){
            int row = r0 + w*8 + rr;
            float p=0.f;
            #pragma unroll
            for (int i=0;i<8;++i){
                int k = lane + 32*i;
                p += Wih[(size_t)row*HD + k]*sx[k];
            }
            #pragma unroll
            for (int o=16;o;o>>=1) p += __shfl_down_sync(0xffffffffu,p,o);
            if (lane==0) g_GX[(size_t)t*1024 + row] = p + bih[row] + bhh[row];
        }
    }
}

// ---------------- sequential recurrence: 64 persistent CTAs ----------------
__global__ void __launch_bounds__(256) k_seq2(const float* __restrict__ Whh,
                                              const int* __restrict__ entity_ids,
                                              const float* __restrict__ Wlen, const float* __restrict__ WlenB,
                                              const float* __restrict__ WentB,
                                              const float* __restrict__ wdW, const float* __restrict__ wdB,
                                              const float* __restrict__ WdW, const float* __restrict__ WdB,
                                              const float* __restrict__ WrB,
                                              float* __restrict__ out)
{
    __shared__ float sWhh[16*HD];
    __shared__ float sWd[4*HD];
    __shared__ float sWT[4*HD];
    __shared__ float sh[HD];
    __shared__ float se[HD];
    __shared__ float sred[8];
    __shared__ float sgate[16];
    __shared__ float sc[4];
    const int b = blockIdx.x, tid = threadIdx.x;
    const float dw = wdW[0], db = wdB[0];

    for (int idx = tid; idx < 16*HD; idx += 256){
        int i = idx>>8, k = idx&255;
        int row = (i>>2)*HD + 4*b + (i&3);       // gate g=i>>2, element r=i&3
        sWhh[idx] = Whh[(size_t)row*HD + k];
    }
    for (int idx = tid; idx < 4*HD; idx += 256){
        int r = idx>>8, k = idx&255;
        sWd[idx] = WdW[(size_t)(4*b+r)*HD + k];
        sWT[idx] = g_WentT[(size_t)(4*b+r)*HD + k];
    }
    if (tid < 4) sc[tid] = 0.f;
    __syncthreads();

    unsigned gen = 0;
    for (int t = 0; t < TT; ++t){
        const float tf = (float)t;
        const int eid = entity_ids[t];

        // ---- phase A: gates + h slice (this block owns h[4b..4b+3]) ----
        sh[tid] = __ldcg(&g_hbuf[t&1][tid]);
        __syncthreads();
        {
            const int i = tid>>4, kq = tid&15;
            const float* wrow = &sWhh[i*HD + kq*16];
            const float* hv = &sh[kq*16];
            float p = 0.f;
            #pragma unroll
            for (int j=0;j<16;++j) p += wrow[j]*hv[j];
            #pragma unroll
            for (int o=8;o;o>>=1) p += __shfl_down_sync(0xffffffffu,p,o,16);
            if (kq==0){
                int row = (i>>2)*HD + 4*b + (i&3);
                sgate[i] = p + g_GX[(size_t)t*1024 + row];
            }
        }
        __syncthreads();
        if (tid < 4){
            float gi = sigf(sgate[0*4+tid]);
            float gf = sigf(sgate[1*4+tid]);
            float gg = tanhf(sgate[2*4+tid]);
            float go = sigf(sgate[3*4+tid]);
            float c = gf*sc[tid] + gi*gg;
            float h = go*tanhf(c);
            sc[tid] = c;
            g_hbuf[(t+1)&1][4*b+tid] = h;
            g_Hmat[(size_t)t*HD + 4*b + tid] = h;
        }
        gridbar(++gen);

        // ---- phase B: full-h consumers ----
        sh[tid] = __ldcg(&g_hbuf[(t+1)&1][tid]);
        se[tid] = __ldcg(&g_ents[(size_t)eid*HD + tid]);
        __syncthreads();
        if (tid < 4) g_Ecur[(size_t)t*HD + 4*b + tid] = se[4*b+tid];

        // pred_e for entity b:  A[b]·h + (dist*w+b)*rowsum(A[b]) + Went_b
        {
            float a = __ldcg(&g_A[(size_t)b*HD + tid]);
            float d1 = bred(a*sh[tid], sred, tid);
            float d2 = bred(a, sred, tid);
            if (tid==0){
                float dist = __ldcg(&g_dists[b]) - tf;
                out[(size_t)t*OUTW + 2 + b] = d1 + (dist*dw + db)*d2 + WentB[0];
            }
        }
        // delta partial for this block's 4 Wdelta rows
        {
            float wsum = 0.f;
            #pragma unroll
            for (int r=0;r<4;++r) wsum += se[4*b+r]*sWd[r*HD+tid];
            float pd = bred(wsum*sh[tid], sred, tid);
            if (tid==0) g_pd[b] = pd;
        }
        if (b == 0){
            // pred_r + norms (eh = e·h, hh = h·h)
            float p0 = bred(g_R2[tid]*sh[tid], sred, tid);
            float p1 = bred(g_R2[HD+tid]*sh[tid], sred, tid);
            float eh = bred(se[tid]*sh[tid], sred, tid);
            float hh = bred(sh[tid]*sh[tid], sred, tid);
            if (tid==0){
                out[(size_t)t*OUTW + 0] = p0 + WrB[0];
                out[(size_t)t*OUTW + 1] = p1 + WrB[0];
                g_eh = eh; g_hh = hh;
            }
            // pred_l (25 rows x 512)
            const int w = tid>>5, lane = tid&31;
            for (int l = w; l < 25; l += 8){
                float p = 0.f;
                #pragma unroll
                for (int i=0;i<16;++i){
                    int idx = lane + 32*i;
                    float x = (idx < HD) ? sh[idx] : se[idx-HD];
                    p += Wlen[(size_t)l*512 + idx]*x;
                }
                #pragma unroll
                for (int o=16;o;o>>=1) p += __shfl_down_sync(0xffffffffu,p,o);
                if (lane==0) out[(size_t)t*OUTW + 66 + l] = p + WlenB[l];
            }
        } else {
            // uniform bred participation
            bred(0.f, sred, tid); bred(0.f, sred, tid);
            bred(0.f, sred, tid); bred(0.f, sred, tid);
        }
        gridbar(++gen);

        // ---- phase C: entity update (u = norm(d*e + (1-d)*h)), scatter, A row refresh ----
        {
            float v = (tid < NB) ? __ldcg(&g_pd[tid]) : 0.f;
            float dot = bred(v, sred, tid);
            float d = sigf(dot + WdB[0]);
            float eh = __ldcg(&g_eh), hh = __ldcg(&g_hh);
            float omd = 1.0f - d;
            float nrm = rsqrtf(d*d + 2.0f*d*omd*eh + omd*omd*hh);  // ||e||=1 invariant
            float u = (d*se[tid] + omd*sh[tid]) * nrm;
            #pragma unroll
            for (int r=0;r<4;++r){
                float pa = bred(u*sWT[r*HD+tid], sred, tid);
                if (tid==0) g_A[(size_t)eid*HD + 4*b + r] = pa;
            }
            if (tid < 4){
                g_ents[(size_t)eid*HD + 4*b + tid] =
                    (d*se[4*b+tid] + omd*sh[4*b+tid]) * nrm;
            }
            if (b==0 && tid==0) g_dists[eid] = tf;
        }
        __syncthreads();   // protect se/sh against next phase A's overwrite
    }
}

// ---------------- Z[t] = h_t + We@ecur_t + We_b ----------------
__global__ void __launch_bounds__(256) k_z(const float* __restrict__ We,
                                           const float* __restrict__ Web)
{
    __shared__ float sx[HD];
    const int tid = threadIdx.x, t = blockIdx.x;
    const int w = tid>>5, lane = tid&31;
    sx[tid] = g_Ecur[(size_t)t*HD + tid];
    __syncthreads();
    #pragma unroll
    for (int rr=0;rr<32;++rr){
        int row = w*32 + rr;
        float p = 0.f;
        #pragma unroll
        for (int i=0;i<8;++i){
            int k = lane + 32*i;
            p += We[(size_t)row*HD + k]*sx[k];
        }
        #pragma unroll
        for (int o=16;o;o>>=1) p += __shfl_down_sync(0xffffffffu,p,o);
        if (lane==0)
            g_Z[(size_t)t*HD + row] = p + g_Hmat[(size_t)t*HD + row] + Web[row];
    }
}

// ---------------- pred_x GEMM: out_W[50257,256] @ Z^T -> out cols 91.. ----------------
#define BM 128
#define BN 128
#define BK 16
__global__ void __launch_bounds__(256) k_out(const float* __restrict__ W,
                                             const float* __restrict__ ob,
                                             float* __restrict__ out)
{
    __shared__ float As[BK][BM];
    __shared__ float Bs[BK][BN];
    const int tid = threadIdx.x;
    const int m0 = blockIdx.x*BM, n0 = blockIdx.y*BN;
    const int tx = tid & 15, ty = tid >> 4;
    float acc[8][8];
    #pragma unroll
    for (int i=0;i<8;++i)
        #pragma unroll
        for (int j=0;j<8;++j) acc[i][j]=0.f;

    for (int k0 = 0; k0 < HD; k0 += BK){
        #pragma unroll
        for (int l=0;l<2;++l){
            int idx = tid + l*256;
            int r = idx >> 2;
            int kk = (idx & 3) * 4;
            int gm = m0 + r;
            float4 v = (gm < VSZ) ? *(const float4*)(W + (size_t)gm*HD + k0 + kk)
                                  : make_float4(0.f,0.f,0.f,0.f);
            As[kk][r]=v.x; As[kk+1][r]=v.y; As[kk+2][r]=v.z; As[kk+3][r]=v.w;
            int gn = n0 + r;
            float4 u = *(const float4*)(g_Z + (size_t)gn*HD + k0 + kk);
            Bs[kk][r]=u.x; Bs[kk+1][r]=u.y; Bs[kk+2][r]=u.z; Bs[kk+3][r]=u.w;
        }
        __syncthreads();
        #pragma unroll
        for (int k=0;k<BK;++k){
            float am[8], bn[8];
            #pragma unroll
            for (int i=0;i<8;++i) am[i]=As[k][ty*8+i];
            #pragma unroll
            for (int j=0;j<8;++j) bn[j]=Bs[k][tx*8+j];
            #pragma unroll
            for (int i=0;i<8;++i)
                #pragma unroll
                for (int j=0;j<8;++j) acc[i][j] += am[i]*bn[j];
        }
        __syncthreads();
    }
    #pragma unroll
    for (int i=0;i<8;++i){
        int v = m0 + ty*8 + i;
        if (v >= VSZ) continue;
        float bias = ob[v];
        #pragma unroll
        for (int j=0;j<8;++j){
            int t = n0 + tx*8 + j;
            out[(size_t)t*OUTW + 91 + v] = acc[i][j] + bias;
        }
    }
}

extern "C" void kernel_launch(void* const* d_in, const int* in_sizes, int n_in,
                              void* d_out, int out_size)
{
    const int*   tokens  = (const int*)  d_in[0];
    const int*   eids    = (const int*)  d_in[1];
    const float* emb     = (const float*)d_in[2];
    const float* W_ih    = (const float*)d_in[3];
    const float* W_hh    = (const float*)d_in[4];
    const float* b_ih    = (const float*)d_in[5];
    const float* b_hh    = (const float*)d_in[6];
    const float* out_W   = (const float*)d_in[7];
    const float* out_b   = (const float*)d_in[8];
    const float* r_emb   = (const float*)d_in[9];
    const float* Wr_W    = (const float*)d_in[10];
    const float* Wr_b    = (const float*)d_in[11];
    const float* Wlen_W  = (const float*)d_in[12];
    const float* Wlen_b  = (const float*)d_in[13];
    const float* Went_W  = (const float*)d_in[14];
    const float* Went_b  = (const float*)d_in[15];
    const float* wdist_W = (const float*)d_in[16];
    const float* wdist_b = (const float*)d_in[17];
    const float* Wdelta_W= (const float*)d_in[18];
    const float* Wdelta_b= (const float*)d_in[19];
    const float* We_W    = (const float*)d_in[20];
    const float* We_b    = (const float*)d_in[21];
    const float* ents0   = (const float*)d_in[22];
    const float* dist0   = (const float*)d_in[23];
    float* out = (float*)d_out;

    k_prep<<<ESZ+1, 256>>>(ents0, dist0, Went_W, r_emb, Wr_W);
    k_gx<<<TT, 256>>>(W_ih, emb, tokens, b_ih, b_hh);
    k_seq2<<<NB, 256>>>(W_hh, eids, Wlen_W, Wlen_b, Went_b,
                        wdist_W, wdist_b, Wdelta_W, Wdelta_b, Wr_b, out);
    k_z<<<TT, 256>>>(We_W, We_b);
    dim3 gg((VSZ + BM - 1)/BM, TT/BN);
    k_out<<<gg, 256>>>(out_W, out_b, out);
}

// round 7
// speedup vs baseline: 2.2565x; 2.2565x over previous
#include <cuda_runtime.h>
#include <math.h>

#define VSZ 50257
#define HD  256
#define ESZ 64
#define TT  2048
#define OUTW 50348   // 2 + 64 + 25 + 50257
#define NBL 32       // persistent LSTM CTAs

// ---------------- device scratch ----------------
__device__ float g_GX[TT*1024];
__device__ float g_Hmat[TT*HD];
__device__ float g_Ecur[TT*HD];
__device__ float g_Uupd[TT*HD];
__device__ float g_Z[TT*HD];
__device__ float g_D[TT*HD];
__device__ float g_G[TT*HD];
__device__ float g_hharr[TT];
__device__ float g_ents[ESZ*HD];
__device__ float g_hbuf[2][HD];
__device__ float g_R2[2*HD];
__device__ float g_wsum[HD];
__device__ unsigned g_bar_cnt;
__device__ volatile unsigned g_bar_gen;

__device__ __forceinline__ float sigf(float x){ return 1.0f/(1.0f+expf(-x)); }

__device__ __forceinline__ float wredxor(float v){
    #pragma unroll
    for (int o=16;o;o>>=1) v += __shfl_xor_sync(0xffffffffu, v, o);
    return v;
}

// block-wide (256 thr) reduce, result broadcast
__device__ __forceinline__ float bred(float v, float* sred, int tid){
    #pragma unroll
    for (int o=16;o;o>>=1) v += __shfl_down_sync(0xffffffffu, v, o);
    if ((tid&31)==0) sred[tid>>5]=v;
    __syncthreads();
    if (tid==0){ float s=0.f; for(int i=0;i<8;++i) s+=sred[i]; sred[0]=s; }
    __syncthreads();
    float r = sred[0];
    __syncthreads();
    return r;
}

// ---------------- prep: R2, wsum, ents copy, hbuf/barrier reset ----------------
__global__ void k_prep(const float* __restrict__ ents0, const float* __restrict__ Went,
                       const float* __restrict__ r_emb, const float* __restrict__ Wr)
{
    const int b = blockIdx.x, tid = threadIdx.x;
    if (b == ESZ){
        for (int r=0;r<2;++r){
            float s=0.f;
            for (int k=0;k<HD;++k) s += r_emb[r*HD+k]*Wr[k*HD+tid];
            g_R2[r*HD+tid] = s;
        }
        float ws=0.f;
        for (int j=0;j<HD;++j) ws += Went[(size_t)tid*HD + j];
        g_wsum[tid] = ws;
        if (tid==0){ g_bar_cnt=0u; g_bar_gen=0u; }
        g_hbuf[0][tid] = 0.f; g_hbuf[1][tid] = 0.f;
    } else {
        g_ents[b*HD+tid] = ents0[b*HD+tid];
    }
}

// ---------------- GX[t][row] = W_ih[row]·emb[tok_t] + b_ih + b_hh ----------------
__global__ void __launch_bounds__(256) k_gx(const float* __restrict__ Wih,
                                            const float* __restrict__ emb,
                                            const int*   __restrict__ tokens,
                                            const float* __restrict__ bih,
                                            const float* __restrict__ bhh)
{
    __shared__ float sx[HD];
    const int tid = threadIdx.x, t = blockIdx.x;
    const int w = tid>>5, lane = tid&31;
    const int tok = tokens[t];
    sx[tid] = emb[(size_t)tok*HD + tid];
    __syncthreads();
    for (int r0=0;r0<1024;r0+=64){
        #pragma unroll
        for (int rr=0;rr<8;++rr){
            int row = r0 + w*8 + rr;
            float p=0.f;
            #pragma unroll
            for (int i=0;i<8;++i){
                int k = lane + 32*i;
                p += Wih[(size_t)row*HD + k]*sx[k];
            }
            #pragma unroll
            for (int o=16;o;o>>=1) p += __shfl_down_sync(0xffffffffu,p,o);
            if (lane==0) g_GX[(size_t)t*1024 + row] = p + bih[row] + bhh[row];
        }
    }
}

// ---------------- pure LSTM recurrence: 32 persistent CTAs, 1 barrier/step ----------------
__global__ void __launch_bounds__(512) k_lstm(const float* __restrict__ Whh)
{
    __shared__ float sW[32*HD];   // 32 gate rows for this CTA's 8 h-elements
    __shared__ float sh[HD];
    __shared__ float sgate[32];
    __shared__ float sc[8];
    const int b = blockIdx.x, tid = threadIdx.x;

    for (int idx = tid; idx < 32*HD; idx += 512){
        int i = idx>>8, k = idx&255;
        int row = (i>>3)*HD + 8*b + (i&7);      // gate g=i>>3, local elem jj=i&7
        sW[idx] = Whh[(size_t)row*HD + k];
    }
    if (tid < 8) sc[tid] = 0.f;
    __syncthreads();

    unsigned gen = 0;
    for (int t = 0; t < TT; ++t){
        if (tid < HD) sh[tid] = __ldcg(&g_hbuf[t&1][tid]);
        __syncthreads();
        {
            const int i = tid>>4, kq = tid&15;
            const float* wrow = &sW[i*HD + kq*16];
            const float* hv = &sh[kq*16];
            float p = 0.f;
            #pragma unroll
            for (int j=0;j<16;++j) p += wrow[j]*hv[j];
            #pragma unroll
            for (int o=8;o;o>>=1) p += __shfl_down_sync(0xffffffffu,p,o,16);
            if (kq==0){
                int row = (i>>3)*HD + 8*b + (i&7);
                sgate[i] = p + g_GX[(size_t)t*1024 + row];
            }
        }
        __syncthreads();
        if (tid < 8){
            float gi = sigf(sgate[0*8+tid]);
            float gf = sigf(sgate[1*8+tid]);
            float gg = tanhf(sgate[2*8+tid]);
            float go = sigf(sgate[3*8+tid]);
            float c = gf*sc[tid] + gi*gg;
            float h = go*tanhf(c);
            sc[tid] = c;
            g_hbuf[(t+1)&1][8*b+tid] = h;
            g_Hmat[(size_t)t*HD + 8*b + tid] = h;
        }
        // single grid barrier
        __syncthreads();
        if (tid==0){
            __threadfence();
            unsigned prev = atomicAdd(&g_bar_cnt, 1u);
            if (prev == NBL-1u){ g_bar_cnt = 0u; __threadfence(); g_bar_gen = gen+1u; }
            else { while (g_bar_gen <= gen) {} __threadfence(); }
        }
        __syncthreads();
        ++gen;
    }
}

// ---------------- batched per-t: D=Wdelta@h, G=Went@h, hh, pred_r ----------------
__global__ void __launch_bounds__(256) k_bat1(const float* __restrict__ Wd,
                                              const float* __restrict__ Went,
                                              const float* __restrict__ WrB,
                                              float* __restrict__ out)
{
    __shared__ float sh[HD];
    __shared__ float sred[8];
    const int t = blockIdx.x, tid = threadIdx.x;
    const int w = tid>>5, lane = tid&31;
    sh[tid] = g_Hmat[(size_t)t*HD + tid];
    __syncthreads();
    #pragma unroll 1
    for (int rr=0; rr<32; ++rr){
        int r = w*32 + rr;
        float pd=0.f, pg=0.f;
        #pragma unroll
        for (int i=0;i<8;++i){
            int k = lane + 32*i;
            float hv = sh[k];
            pd += Wd[(size_t)r*HD + k]*hv;
            pg += Went[(size_t)r*HD + k]*hv;
        }
        #pragma unroll
        for (int o=16;o;o>>=1){
            pd += __shfl_down_sync(0xffffffffu,pd,o);
            pg += __shfl_down_sync(0xffffffffu,pg,o);
        }
        if (lane==0){
            g_D[(size_t)t*HD + r] = pd;
            g_G[(size_t)t*HD + r] = pg;
        }
    }
    float v = sh[tid];
    float hh = bred(v*v, sred, tid);
    float p0 = bred(g_R2[tid]*v, sred, tid);
    float p1 = bred(g_R2[HD+tid]*v, sred, tid);
    if (tid==0){
        g_hharr[t] = hh;
        out[(size_t)t*OUTW + 0] = p0 + WrB[0];
        out[(size_t)t*OUTW + 1] = p1 + WrB[0];
    }
}

// ---------------- sequential entity chain: ONE warp ----------------
__global__ void k_ent(const int* __restrict__ eids, const float* __restrict__ WdB)
{
    const int lane = threadIdx.x;
    const float wdb = WdB[0];
    int eid = eids[0];
    float Dc[8], hc[8];
    #pragma unroll
    for (int i=0;i<8;++i){
        Dc[i] = g_D[lane + 32*i];
        hc[i] = g_Hmat[lane + 32*i];
    }
    for (int t = 0; t < TT; ++t){
        int neid = 0; float Dn[8], hn[8];
        if (t+1 < TT){
            neid = eids[t+1];
            #pragma unroll
            for (int i=0;i<8;++i){
                Dn[i] = g_D[(size_t)(t+1)*HD + lane + 32*i];
                hn[i] = g_Hmat[(size_t)(t+1)*HD + lane + 32*i];
            }
        }
        float e[8];
        #pragma unroll
        for (int i=0;i<8;++i) e[i] = g_ents[(size_t)eid*HD + lane + 32*i];
        float ad=0.f, aeh=0.f, aee=0.f;
        #pragma unroll
        for (int i=0;i<8;++i){ ad += e[i]*Dc[i]; aeh += e[i]*hc[i]; aee += e[i]*e[i]; }
        ad = wredxor(ad); aeh = wredxor(aeh); aee = wredxor(aee);
        float d = sigf(ad + wdb), omd = 1.0f - d;
        float nrm = rsqrtf(d*d*aee + 2.0f*d*omd*aeh + omd*omd*g_hharr[t]);
        #pragma unroll
        for (int i=0;i<8;++i){
            int k = lane + 32*i;
            float u = (d*e[i] + omd*hc[i]) * nrm;
            g_Ecur[(size_t)t*HD + k] = e[i];
            g_Uupd[(size_t)t*HD + k] = u;
            g_ents[(size_t)eid*HD + k] = u;
        }
        eid = neid;
        #pragma unroll
        for (int i=0;i<8;++i){ Dc[i]=Dn[i]; hc[i]=hn[i]; }
    }
}

// ---------------- pred_e: 64 one-warp CTAs, entity e walks its versions ----------------
__global__ void k_prede(const float* __restrict__ ents0, const int* __restrict__ eids,
                        const float* __restrict__ wdW, const float* __restrict__ wdB,
                        const float* __restrict__ WentB, float* __restrict__ out)
{
    const int e = blockIdx.x, lane = threadIdx.x;
    const float wd = wdW[0], db = wdB[0], wb = WentB[0];
    float ek[8], ws[8];
    #pragma unroll
    for (int i=0;i<8;++i){
        ek[i] = ents0[(size_t)e*HD + lane + 32*i];
        ws[i] = g_wsum[lane + 32*i];
    }
    float p = 0.f;
    #pragma unroll
    for (int i=0;i<8;++i) p += ek[i]*ws[i];
    p = wredxor(p);
    float dist = 0.f;
    int eidc = eids[0];
    float Gc[8];
    #pragma unroll
    for (int i=0;i<8;++i) Gc[i] = g_G[lane + 32*i];
    for (int t = 0; t < TT; ++t){
        int eidn = 0; float Gn[8];
        if (t+1 < TT){
            eidn = eids[t+1];
            #pragma unroll
            for (int i=0;i<8;++i) Gn[i] = g_G[(size_t)(t+1)*HD + lane + 32*i];
        }
        float q = 0.f;
        #pragma unroll
        for (int i=0;i<8;++i) q += ek[i]*Gc[i];
        q = wredxor(q);
        if (lane==0)
            out[(size_t)t*OUTW + 2 + e] = q + ((dist - (float)t)*wd + db)*p + wb;
        if (eidc == e){
            float pp = 0.f;
            #pragma unroll
            for (int i=0;i<8;++i){
                ek[i] = g_Uupd[(size_t)t*HD + lane + 32*i];
                pp += ek[i]*ws[i];
            }
            p = wredxor(pp);
            dist = (float)t;
        }
        eidc = eidn;
        #pragma unroll
        for (int i=0;i<8;++i) Gc[i] = Gn[i];
    }
}

// ---------------- Z[t] = h + We@ecur + We_b ; plus pred_l ----------------
__global__ void __launch_bounds__(256) k_z(const float* __restrict__ We,
                                           const float* __restrict__ Web,
                                           const float* __restrict__ Wlen,
                                           const float* __restrict__ WlenB,
                                           float* __restrict__ out)
{
    __shared__ float sx[HD];
    __shared__ float shh[HD];
    const int tid = threadIdx.x, t = blockIdx.x;
    const int w = tid>>5, lane = tid&31;
    sx[tid]  = g_Ecur[(size_t)t*HD + tid];
    shh[tid] = g_Hmat[(size_t)t*HD + tid];
    __syncthreads();
    #pragma unroll 1
    for (int rr=0;rr<32;++rr){
        int row = w*32 + rr;
        float p = 0.f;
        #pragma unroll
        for (int i=0;i<8;++i){
            int k = lane + 32*i;
            p += We[(size_t)row*HD + k]*sx[k];
        }
        #pragma unroll
        for (int o=16;o;o>>=1) p += __shfl_down_sync(0xffffffffu,p,o);
        if (lane==0)
            g_Z[(size_t)t*HD + row] = p + shh[row] + Web[row];
    }
    for (int l = w; l < 25; l += 8){
        float p = 0.f;
        #pragma unroll
        for (int i=0;i<16;++i){
            int idx = lane + 32*i;
            float x = (idx < HD) ? shh[idx] : sx[idx-HD];
            p += Wlen[(size_t)l*512 + idx]*x;
        }
        #pragma unroll
        for (int o=16;o;o>>=1) p += __shfl_down_sync(0xffffffffu,p,o);
        if (lane==0) out[(size_t)t*OUTW + 66 + l] = p + WlenB[l];
    }
}

// ---------------- pred_x GEMM: out_W[50257,256] @ Z^T ----------------
#define BM 128
#define BN 128
#define BK 16
__global__ void __launch_bounds__(256) k_out(const float* __restrict__ W,
                                             const float* __restrict__ ob,
                                             float* __restrict__ out)
{
    __shared__ float As[BK][BM];
    __shared__ float Bs[BK][BN];
    const int tid = threadIdx.x;
    const int m0 = blockIdx.x*BM, n0 = blockIdx.y*BN;
    const int tx = tid & 15, ty = tid >> 4;
    float acc[8][8];
    #pragma unroll
    for (int i=0;i<8;++i)
        #pragma unroll
        for (int j=0;j<8;++j) acc[i][j]=0.f;

    for (int k0 = 0; k0 < HD; k0 += BK){
        #pragma unroll
        for (int l=0;l<2;++l){
            int idx = tid + l*256;
            int r = idx >> 2;
            int kk = (idx & 3) * 4;
            int gm = m0 + r;
            float4 v = (gm < VSZ) ? *(const float4*)(W + (size_t)gm*HD + k0 + kk)
                                  : make_float4(0.f,0.f,0.f,0.f);
            As[kk][r]=v.x; As[kk+1][r]=v.y; As[kk+2][r]=v.z; As[kk+3][r]=v.w;
            int gn = n0 + r;
            float4 u = *(const float4*)(g_Z + (size_t)gn*HD + k0 + kk);
            Bs[kk][r]=u.x; Bs[kk+1][r]=u.y; Bs[kk+2][r]=u.z; Bs[kk+3][r]=u.w;
        }
        __syncthreads();
        #pragma unroll
        for (int k=0;k<BK;++k){
            float am[8], bn[8];
            #pragma unroll
            for (int i=0;i<8;++i) am[i]=As[k][ty*8+i];
            #pragma unroll
            for (int j=0;j<8;++j) bn[j]=Bs[k][tx*8+j];
            #pragma unroll
            for (int i=0;i<8;++i)
                #pragma unroll
                for (int j=0;j<8;++j) acc[i][j] += am[i]*bn[j];
        }
        __syncthreads();
    }
    #pragma unroll
    for (int i=0;i<8;++i){
        int v = m0 + ty*8 + i;
        if (v >= VSZ) continue;
        float bias = ob[v];
        #pragma unroll
        for (int j=0;j<8;++j){
            int t = n0 + tx*8 + j;
            out[(size_t)t*OUTW + 91 + v] = acc[i][j] + bias;
        }
    }
}

extern "C" void kernel_launch(void* const* d_in, const int* in_sizes, int n_in,
                              void* d_out, int out_size)
{
    const int*   tokens  = (const int*)  d_in[0];
    const int*   eids    = (const int*)  d_in[1];
    const float* emb     = (const float*)d_in[2];
    const float* W_ih    = (const float*)d_in[3];
    const float* W_hh    = (const float*)d_in[4];
    const float* b_ih    = (const float*)d_in[5];
    const float* b_hh    = (const float*)d_in[6];
    const float* out_W   = (const float*)d_in[7];
    const float* out_b   = (const float*)d_in[8];
    const float* r_emb   = (const float*)d_in[9];
    const float* Wr_W    = (const float*)d_in[10];
    const float* Wr_b    = (const float*)d_in[11];
    const float* Wlen_W  = (const float*)d_in[12];
    const float* Wlen_b  = (const float*)d_in[13];
    const float* Went_W  = (const float*)d_in[14];
    const float* Went_b  = (const float*)d_in[15];
    const float* wdist_W = (const float*)d_in[16];
    const float* wdist_b = (const float*)d_in[17];
    const float* Wdelta_W= (const float*)d_in[18];
    const float* Wdelta_b= (const float*)d_in[19];
    const float* We_W    = (const float*)d_in[20];
    const float* We_b    = (const float*)d_in[21];
    const float* ents0   = (const float*)d_in[22];
    float* out = (float*)d_out;

    k_prep<<<ESZ+1, 256>>>(ents0, Went_W, r_emb, Wr_W);
    k_gx<<<TT, 256>>>(W_ih, emb, tokens, b_ih, b_hh);
    k_lstm<<<NBL, 512>>>(W_hh);
    k_bat1<<<TT, 256>>>(Wdelta_W, Went_W, Wr_b, out);
    k_ent<<<1, 32>>>(eids, Wdelta_b);
    k_prede<<<ESZ, 32>>>(ents0, eids, wdist_W, wdist_b, Went_b, out);
    k_z<<<TT, 256>>>(We_W, We_b, Wlen_W, Wlen_b, out);
    dim3 gg((VSZ + BM - 1)/BM, TT/BN);
    k_out<<<gg, 256>>>(out_W, out_b, out);
}